// round 9
// baseline (speedup 1.0000x reference)
#include <cuda_runtime.h>
#include <cuda_bf16.h>
#include <math_constants.h>
#include <cstdint>

#define NN 50000
#define NE 1600000
#define FIN 264
#define FH 48
#define FC 144
#define FM 64
#define KPAD 272                      // 264 padded to 17 chunks of 16
#define GM 64                         // gemm rows per CTA
#define GSTR 24                       // smem row stride in u16 (48B, conflict-free)
#define NCH 17

#define NB_EDGES 6250                 // NE/256
#define NB_WPACK 153                  // ceil(FC*KPAD/256)
#define NB_GEMM  782                  // ceil(NN/64) = 782 (64*782 = 50048)

typedef unsigned long long u64;
typedef unsigned int u32;
typedef unsigned short u16;

// ---------------- scratch (static __device__ globals; zero-init, no allocs) ----------------
__device__ int   g_row[NE];
__device__ int   g_col[NE];
__device__ float g_deg[NN];           // Σ edge weight; RE-ZEROED by k_scan each call
__device__ int   g_count[NN];         // in-degree; RE-ZEROED by k_scan each call
__device__ float g_dis[NN];           // rsqrt(1+deg)
__device__ int   g_off[NN + 1];
__device__ int   g_cursor[NN];
__device__ int2  g_csr[NE];
__device__ float g_H[(size_t)NN * FC];
__device__ float g_Y[(size_t)NN * FC];
__device__ u16   g_Wh[(size_t)FC * KPAD];     // [WM|WA|WS] hi, n-major (transposed)
__device__ u16   g_Wl[(size_t)FC * KPAD];     // lo

// ---------------- helpers ----------------
__device__ __forceinline__ void ffma2(u64& d, u64 a, u64 b) {
    asm("fma.rn.f32x2 %0, %1, %2, %0;" : "+l"(d) : "l"(a), "l"(b));
}
__device__ __forceinline__ u64 dup2(float v) {
    u32 u = __float_as_uint(v);
    return (u64)u | ((u64)u << 32);
}
__device__ __forceinline__ float lo2(u64 v) { return __uint_as_float((u32)v); }
__device__ __forceinline__ float hi2(u64 v) { return __uint_as_float((u32)(v >> 32)); }
__device__ __forceinline__ u32 smem_u32(const void* p) {
    u32 a;
    asm("{ .reg .u64 t; cvta.to.shared.u64 t, %1; cvt.u32.u64 %0, t; }" : "=r"(a) : "l"(p));
    return a;
}
__device__ __forceinline__ void cpa16(u32 dst, const void* src) {
    asm volatile("cp.async.cg.shared.global [%0], [%1], 16;" :: "r"(dst), "l"(src));
}
#define CPA_COMMIT() asm volatile("cp.async.commit_group;" ::: "memory")
#define CPA_WAIT1()  asm volatile("cp.async.wait_group 1;" ::: "memory")
#define CPA_WAIT0()  asm volatile("cp.async.wait_group 0;" ::: "memory")

// bf16 HMMA: D[16x8] += A[16x16] * B[16x8], fp32 accum (baseline PTX, fallback HMMA on sm_103)
__device__ __forceinline__ void mma_bf16(float* c, u32 a0, u32 a1, u32 a2, u32 a3, u32 b0, u32 b1) {
    asm volatile(
        "mma.sync.aligned.m16n8k16.row.col.f32.bf16.bf16.f32 "
        "{%0,%1,%2,%3}, {%4,%5,%6,%7}, {%8,%9}, {%0,%1,%2,%3};"
        : "+f"(c[0]), "+f"(c[1]), "+f"(c[2]), "+f"(c[3])
        : "r"(a0), "r"(a1), "r"(a2), "r"(a3), "r"(b0), "r"(b1));
}

__device__ __forceinline__ void split_bf16(float v, u16& h, u16& l) {
    __nv_bfloat16 hh = __float2bfloat16(v);
    float r = v - __bfloat162float(hh);
    __nv_bfloat16 ll = __float2bfloat16(r);
    h = __bfloat16_as_ushort(hh);
    l = __bfloat16_as_ushort(ll);
}

// ---------------- weights -> split-bf16, n-major [144][KPAD] ----------------
__global__ void k_wpack(const float* __restrict__ WM, const float* __restrict__ WA,
                        const float* __restrict__ WS) {
    int idx = blockIdx.x * blockDim.x + threadIdx.x;
    if (idx < FC * KPAD) {
        int c = idx / KPAD, k = idx - c * KPAD;
        float v = 0.f;
        if (k < FIN)
            v = (c < 48) ? WM[k * FH + c] : (c < 96) ? WA[k * FH + c - 48] : WS[k * FH + c - 96];
        u16 h, l;
        split_bf16(v, h, l);
        g_Wh[(size_t)c * KPAD + k] = h;
        g_Wl[(size_t)c * KPAD + k] = l;
    }
}

// ---------------- extract edges + degree/in-degree histogram ----------------
__global__ __launch_bounds__(256) void k_edges(const int* __restrict__ ei32,
                                               const float* __restrict__ ew) {
    __shared__ int s_is64;
    int tid = threadIdx.x;
    if (tid == 0) {
        int all0 = 1;
        for (int k = 0; k < 32; k++)
            if (ei32[2 * k + 1] != 0) { all0 = 0; break; }
        s_is64 = all0;   // int64 LE with values<2^31 -> odd words all zero
    }
    __syncthreads();
    int e = blockIdx.x * 256 + tid;
    if (e < NE) {
        int row, col;
        if (s_is64) { row = ei32[2 * e]; col = ei32[2 * (NE + e)]; }
        else        { row = ei32[e];     col = ei32[NE + e]; }
        g_row[e] = row;
        g_col[e] = col;
        atomicAdd(&g_deg[col], ew[e]);
        atomicAdd(&g_count[col], 1);
    }
}

// ---------------- scan: dis = rsqrt(1+deg), exclusive scan of counts, reset accumulators ----------------
__global__ void k_scan() {
    __shared__ int s[1024];
    int tid = threadIdx.x;
    for (int i = tid; i < NN; i += 1024) {
        g_dis[i] = rsqrtf(1.0f + g_deg[i]);
        g_deg[i] = 0.f;                      // reset for next graph replay
    }

    const int CH = (NN + 1023) / 1024;
    int lo = tid * CH;
    int hi = lo + CH; if (hi > NN) hi = NN;
    int sum = 0;
    for (int i = lo; i < hi; i++) sum += g_count[i];
    s[tid] = sum;
    __syncthreads();
    for (int off = 1; off < 1024; off <<= 1) {
        int t = (tid >= off) ? s[tid - off] : 0;
        __syncthreads();
        s[tid] += t;
        __syncthreads();
    }
    int run = s[tid] - sum;
    for (int i = lo; i < hi; i++) {
        int c = g_count[i];
        g_off[i] = run; g_cursor[i] = run;
        g_count[i] = 0;                      // reset for next graph replay
        run += c;
    }
    if (tid == 1023) g_off[NN] = run;
}

// ---------------- CSR scatter (standalone: full occupancy) ----------------
__global__ void k_csr(const float* __restrict__ ew) {
    int e = blockIdx.x * blockDim.x + threadIdx.x;
    if (e < NE) {
        int row = g_row[e];
        int col = g_col[e];
        float nrm = g_dis[row] * ew[e] * g_dis[col];
        int pos = atomicAdd(&g_cursor[col], 1);
        g_csr[pos] = make_int2(row, __float_as_int(nrm));
    }
}

// ---------------- GEMM1 on HMMA: H = x @ [WM|WA|WS], in-kernel fp32->split-bf16 ----------------
__global__ void __launch_bounds__(128, 4) k_gemm(const float* __restrict__ x,
                                                 const float* __restrict__ bS) {
    __shared__ u16   sA[2][2][GM * GSTR];    // [buf][hi/lo][row*24 + k] : 12 KB
    __shared__ u16   sB[2][2][FC * GSTR];    // [buf][hi/lo][n*24 + k]   : 27 KB
    __shared__ float sX[2][GM * 16];         // raw fp32 x tile          : 8 KB
    int tid = threadIdx.x;
    int w = tid >> 5, lane = tid & 31;
    int gr = lane >> 2, kp = lane & 3;
    int row0 = blockIdx.x * GM;

    float acc[18][4];
#pragma unroll
    for (int i = 0; i < 18; i++) { acc[i][0] = acc[i][1] = acc[i][2] = acc[i][3] = 0.f; }

    auto load_ab = [&](int ch) {
        int buf = ch & 1;
        int kt = ch * 16;
        // X raw: 64 rows x 16 fp32 = 256 granules of 16B (2 per thread); zero-fill OOB
#pragma unroll
        for (int l = 0; l < 2; l++) {
            int idx = tid + l * 128;
            int row = idx >> 2, g = idx & 3;
            int grow = row0 + row;
            int k0 = kt + g * 4;
            if (grow < NN && k0 + 4 <= FIN) {
                cpa16(smem_u32(&sX[buf][row * 16 + g * 4]), &x[(size_t)grow * FIN + k0]);
            } else {
                *(float4*)&sX[buf][row * 16 + g * 4] = make_float4(0.f, 0.f, 0.f, 0.f);
            }
        }
        // B: 144 rows x 16 bf16 x 2 splits = 576 granules
#pragma unroll
        for (int l = 0; l < 5; l++) {
            int idx = tid + l * 128;
            if (idx < 576) {
                int split = (idx >= 288) ? 1 : 0;
                int e = idx - split * 288;
                int n = e >> 1, half = e & 1;
                const u16* src = (split ? g_Wl : g_Wh) + (size_t)n * KPAD + kt + half * 8;
                cpa16(smem_u32(&sB[buf][split][n * GSTR + half * 8]), src);
            }
        }
        CPA_COMMIT();
    };

    load_ab(0);
    load_ab(1);

    int aoff = (w * 16 + gr) * GSTR + kp * 2;   // u16 index of a0
    int boff = gr * GSTR + kp * 2;              // u16 index within n-tile

    for (int ch = 0; ch < NCH; ch++) {
        int buf = ch & 1;
        if (ch < NCH - 1) CPA_WAIT1(); else CPA_WAIT0();
        __syncthreads();

        // convert raw fp32 tile -> split-bf16 sA (runs on idle fma/alu pipes)
        {
            int row = tid >> 1, half = tid & 1;
            const float* src = &sX[buf][row * 16 + half * 8];
            u32 h4[4], l4[4];
#pragma unroll
            for (int j = 0; j < 4; j++) {
                u16 h0, l0, h1, l1;
                split_bf16(src[j * 2], h0, l0);
                split_bf16(src[j * 2 + 1], h1, l1);
                h4[j] = (u32)h0 | ((u32)h1 << 16);
                l4[j] = (u32)l0 | ((u32)l1 << 16);
            }
            *(uint4*)&sA[buf][0][row * GSTR + half * 8] = make_uint4(h4[0], h4[1], h4[2], h4[3]);
            *(uint4*)&sA[buf][1][row * GSTR + half * 8] = make_uint4(l4[0], l4[1], l4[2], l4[3]);
        }
        __syncthreads();

        u32 ah0 = *(const u32*)&sA[buf][0][aoff];
        u32 ah1 = *(const u32*)&sA[buf][0][aoff + 8 * GSTR];
        u32 ah2 = *(const u32*)&sA[buf][0][aoff + 8];
        u32 ah3 = *(const u32*)&sA[buf][0][aoff + 8 * GSTR + 8];
        u32 al0 = *(const u32*)&sA[buf][1][aoff];
        u32 al1 = *(const u32*)&sA[buf][1][aoff + 8 * GSTR];
        u32 al2 = *(const u32*)&sA[buf][1][aoff + 8];
        u32 al3 = *(const u32*)&sA[buf][1][aoff + 8 * GSTR + 8];

#pragma unroll
        for (int nt = 0; nt < 18; nt++) {
            int bo = nt * 8 * GSTR + boff;
            u32 bh0 = *(const u32*)&sB[buf][0][bo];
            u32 bh1 = *(const u32*)&sB[buf][0][bo + 8];
            u32 bl0 = *(const u32*)&sB[buf][1][bo];
            u32 bl1 = *(const u32*)&sB[buf][1][bo + 8];
            mma_bf16(acc[nt], ah0, ah1, ah2, ah3, bh0, bh1);   // xh*wh
            mma_bf16(acc[nt], ah0, ah1, ah2, ah3, bl0, bl1);   // xh*wl
            mma_bf16(acc[nt], al0, al1, al2, al3, bh0, bh1);   // xl*wh
        }
        __syncthreads();
        if (ch + 2 < NCH) load_ab(ch + 2);
    }

    // epilogue: thread holds rows (gr, gr+8) of warp slab, cols nt*8 + kp*2 (+1)
    int r1 = row0 + w * 16 + gr;
    int r2 = r1 + 8;
#pragma unroll
    for (int nt = 0; nt < 18; nt++) {
        int n0 = nt * 8 + kp * 2;
        float v0 = acc[nt][0], v1 = acc[nt][1], v2 = acc[nt][2], v3 = acc[nt][3];
        if (n0 >= 96) {
            float b0 = bS[n0 - 96], b1 = bS[n0 - 95];
            v0 = fmaxf(v0 + b0, 0.f); v1 = fmaxf(v1 + b1, 0.f);
            v2 = fmaxf(v2 + b0, 0.f); v3 = fmaxf(v3 + b1, 0.f);
        }
        if (r1 < NN) *(float2*)&g_H[(size_t)r1 * FC + n0] = make_float2(v0, v1);
        if (r2 < NN) *(float2*)&g_H[(size_t)r2 * FC + n0] = make_float2(v2, v3);
    }
}

// ---------------- aggregation: 1 warp per node, 8 lanes per edge, no atomics ----------------
__global__ __launch_bounds__(256) void k_agg(const float* __restrict__ bM, const float* __restrict__ bA) {
    __shared__ float sb[96];
    int tid = threadIdx.x;
    if (tid < 96) sb[tid] = (tid < 48) ? bM[tid] : bA[tid - 48];
    __syncthreads();

    int wid = tid >> 5;
    int i = blockIdx.x * 8 + wid;
    int lane = tid & 31;
    int group = lane >> 3;
    int gl = lane & 7;
    bool m1 = (gl < 4);
    const float NINF = -CUDART_INF_F;

    const float* Hrow = g_H + (size_t)i * FC;
    float4 acc0, acc1, acc2;
    if (group == 0) {
        float dii = g_dis[i];
        float sm = dii * dii;
        float4 v0 = *(const float4*)(Hrow + gl * 4);
        float4 v1 = *(const float4*)(Hrow + 32 + gl * 4);
        float4 v2 = *(const float4*)(Hrow + 64 + gl * 4);
        acc0 = make_float4(sm * v0.x, sm * v0.y, sm * v0.z, sm * v0.w);
        acc1 = make_float4(sm * v1.x, sm * v1.y, sm * v1.z, sm * v1.w);
        acc2 = make_float4(sm * v2.x, sm * v2.y, sm * v2.z, sm * v2.w);
    } else {
        acc0 = make_float4(NINF, NINF, NINF, NINF);
        float i1 = m1 ? NINF : 0.f;
        acc1 = make_float4(i1, i1, i1, i1);
        acc2 = make_float4(0.f, 0.f, 0.f, 0.f);
    }

    int s0 = g_off[i], s1 = g_off[i + 1];
    for (int j = s0 + group; j < s1; j += 4) {
        int2 p = g_csr[j];
        const float* Hr = g_H + (size_t)p.x * FC;
        float nrm = __int_as_float(p.y);
        float4 v0 = *(const float4*)(Hr + gl * 4);
        float4 v1 = *(const float4*)(Hr + 32 + gl * 4);
        float4 v2 = *(const float4*)(Hr + 64 + gl * 4);
        acc0.x = fmaxf(acc0.x, nrm * v0.x); acc0.y = fmaxf(acc0.y, nrm * v0.y);
        acc0.z = fmaxf(acc0.z, nrm * v0.z); acc0.w = fmaxf(acc0.w, nrm * v0.w);
        if (m1) {
            acc1.x = fmaxf(acc1.x, nrm * v1.x); acc1.y = fmaxf(acc1.y, nrm * v1.y);
            acc1.z = fmaxf(acc1.z, nrm * v1.z); acc1.w = fmaxf(acc1.w, nrm * v1.w);
        } else {
            acc1.x = fmaf(nrm, v1.x, acc1.x); acc1.y = fmaf(nrm, v1.y, acc1.y);
            acc1.z = fmaf(nrm, v1.z, acc1.z); acc1.w = fmaf(nrm, v1.w, acc1.w);
        }
        acc2.x = fmaf(nrm, v2.x, acc2.x); acc2.y = fmaf(nrm, v2.y, acc2.y);
        acc2.z = fmaf(nrm, v2.z, acc2.z); acc2.w = fmaf(nrm, v2.w, acc2.w);
    }

#pragma unroll
    for (int d = 8; d <= 16; d <<= 1) {
        float t;
        t = __shfl_xor_sync(0xffffffffu, acc0.x, d); acc0.x = fmaxf(acc0.x, t);
        t = __shfl_xor_sync(0xffffffffu, acc0.y, d); acc0.y = fmaxf(acc0.y, t);
        t = __shfl_xor_sync(0xffffffffu, acc0.z, d); acc0.z = fmaxf(acc0.z, t);
        t = __shfl_xor_sync(0xffffffffu, acc0.w, d); acc0.w = fmaxf(acc0.w, t);
        t = __shfl_xor_sync(0xffffffffu, acc1.x, d); acc1.x = m1 ? fmaxf(acc1.x, t) : acc1.x + t;
        t = __shfl_xor_sync(0xffffffffu, acc1.y, d); acc1.y = m1 ? fmaxf(acc1.y, t) : acc1.y + t;
        t = __shfl_xor_sync(0xffffffffu, acc1.z, d); acc1.z = m1 ? fmaxf(acc1.z, t) : acc1.z + t;
        t = __shfl_xor_sync(0xffffffffu, acc1.w, d); acc1.w = m1 ? fmaxf(acc1.w, t) : acc1.w + t;
        t = __shfl_xor_sync(0xffffffffu, acc2.x, d); acc2.x += t;
        t = __shfl_xor_sync(0xffffffffu, acc2.y, d); acc2.y += t;
        t = __shfl_xor_sync(0xffffffffu, acc2.z, d); acc2.z += t;
        t = __shfl_xor_sync(0xffffffffu, acc2.w, d); acc2.w += t;
    }

    float* Yrow = g_Y + (size_t)i * FC;
    if (group == 0) {
        int o0 = gl * 4, o1 = 32 + gl * 4, o2 = 64 + gl * 4;
        float4 y0 = make_float4(fmaxf(acc0.x + sb[o0 + 0], 0.f), fmaxf(acc0.y + sb[o0 + 1], 0.f),
                                fmaxf(acc0.z + sb[o0 + 2], 0.f), fmaxf(acc0.w + sb[o0 + 3], 0.f));
        float4 y1 = make_float4(fmaxf(acc1.x + sb[o1 + 0], 0.f), fmaxf(acc1.y + sb[o1 + 1], 0.f),
                                fmaxf(acc1.z + sb[o1 + 2], 0.f), fmaxf(acc1.w + sb[o1 + 3], 0.f));
        float4 y2 = make_float4(fmaxf(acc2.x + sb[o2 + 0], 0.f), fmaxf(acc2.y + sb[o2 + 1], 0.f),
                                fmaxf(acc2.z + sb[o2 + 2], 0.f), fmaxf(acc2.w + sb[o2 + 3], 0.f));
        *(float4*)(Yrow + o0) = y0;
        *(float4*)(Yrow + o1) = y1;
        *(float4*)(Yrow + o2) = y2;
    }
    if (lane >= 8 && lane < 20) {
        int o = 96 + (lane - 8) * 4;
        *(float4*)(Yrow + o) = *(const float4*)(Hrow + o);
    }
}

// ---------------- MLP head: out = relu(Y @ W1 + b1) @ W2 + b2  — FFMA2 ----------------
__global__ __launch_bounds__(256) void k_mlp(const float* __restrict__ W1, const float* __restrict__ b1,
                                             const float* __restrict__ W2, const float* __restrict__ b2,
                                             float* __restrict__ out) {
    __shared__ float W1s[FC * FM];
    __shared__ float As[16][132];
    __shared__ float b1s[FM], W2s[FM];
    int tid = threadIdx.x;
    for (int idx = tid; idx < FC * FM; idx += 256) W1s[idx] = W1[idx];
    if (tid < FM) { b1s[tid] = b1[tid]; W2s[tid] = W2[tid]; }
    __syncthreads();

    int tx = tid & 15, ty = tid >> 4;
    int row0 = blockIdx.x * 128;
    u64 acc[8][2];
#pragma unroll
    for (int r = 0; r < 8; r++) { acc[r][0] = 0ull; acc[r][1] = 0ull; }

    for (int kt = 0; kt < FC; kt += 16) {
        {
            int m = tid >> 1;
            int kb = (tid & 1) * 8;
            int row = row0 + m;
            float4 v0 = make_float4(0.f, 0.f, 0.f, 0.f), v1 = v0;
            if (row < NN) {
                v0 = *(const float4*)&g_Y[(size_t)row * FC + kt + kb];
                v1 = *(const float4*)&g_Y[(size_t)row * FC + kt + kb + 4];
            }
            As[kb + 0][m] = v0.x; As[kb + 1][m] = v0.y; As[kb + 2][m] = v0.z; As[kb + 3][m] = v0.w;
            As[kb + 4][m] = v1.x; As[kb + 5][m] = v1.y; As[kb + 6][m] = v1.z; As[kb + 7][m] = v1.w;
        }
        __syncthreads();
#pragma unroll
        for (int kk = 0; kk < 16; kk++) {
            u64 bb0 = *(const u64*)&W1s[(kt + kk) * FM + tx * 4];
            u64 bb1 = *(const u64*)&W1s[(kt + kk) * FM + tx * 4 + 2];
#pragma unroll
            for (int r = 0; r < 8; r++) {
                u64 aa = dup2(As[kk][ty * 8 + r]);
                ffma2(acc[r][0], aa, bb0);
                ffma2(acc[r][1], aa, bb1);
            }
        }
        __syncthreads();
    }

    float part[8];
    int c0 = tx * 4;
#pragma unroll
    for (int r = 0; r < 8; r++) {
        float t0 = fmaxf(lo2(acc[r][0]) + b1s[c0 + 0], 0.f);
        float t1 = fmaxf(hi2(acc[r][0]) + b1s[c0 + 1], 0.f);
        float t2 = fmaxf(lo2(acc[r][1]) + b1s[c0 + 2], 0.f);
        float t3 = fmaxf(hi2(acc[r][1]) + b1s[c0 + 3], 0.f);
        part[r] = t0 * W2s[c0] + t1 * W2s[c0 + 1] + t2 * W2s[c0 + 2] + t3 * W2s[c0 + 3];
    }
#pragma unroll
    for (int d = 1; d < 16; d <<= 1)
#pragma unroll
        for (int r = 0; r < 8; r++) part[r] += __shfl_xor_sync(0xffffffffu, part[r], d);

    if (tx == 0) {
        float bb = b2[0];
#pragma unroll
        for (int r = 0; r < 8; r++) {
            int row = row0 + ty * 8 + r;
            if (row < NN) out[row] = part[r] + bb;
        }
    }
}

// ---------------- launch: fork-join two independent chains inside capture ----------------
// origin:  wpack ───────────────► gemm ──(wait e1)─► agg ─► mlp
// side s1: (wait e0) edges ► scan ► csr ──record e1─┘
extern "C" void kernel_launch(void* const* d_in, const int* in_sizes, int n_in,
                              void* d_out, int out_size) {
    const float* x  = (const float*)d_in[0];
    const int*   ei = (const int*)d_in[1];
    const float* ew = (const float*)d_in[2];
    const float* WM = (const float*)d_in[3];
    const float* bM = (const float*)d_in[4];
    const float* WA = (const float*)d_in[5];
    const float* bA = (const float*)d_in[6];
    const float* WS = (const float*)d_in[7];
    const float* bS = (const float*)d_in[8];
    const float* W1 = (const float*)d_in[9];
    const float* b1 = (const float*)d_in[10];
    const float* W2 = (const float*)d_in[11];
    const float* b2 = (const float*)d_in[12];
    float* out = (float*)d_out;

    cudaStream_t s1;
    cudaEvent_t e0, e1;
    cudaStreamCreateWithFlags(&s1, cudaStreamNonBlocking);
    cudaEventCreateWithFlags(&e0, cudaEventDisableTiming);
    cudaEventCreateWithFlags(&e1, cudaEventDisableTiming);

    cudaEventRecord(e0, 0);                 // fork from capture origin
    cudaStreamWaitEvent(s1, e0, 0);

    k_wpack<<<NB_WPACK, 256>>>(WM, WA, WS);           // launch 0 (origin)
    k_edges<<<NB_EDGES, 256, 0, s1>>>(ei, ew);        // launch 1 (s1)
    k_scan<<<1, 1024, 0, s1>>>();                     // launch 2 (s1)
    k_csr<<<NB_EDGES, 256, 0, s1>>>(ew);              // launch 3 (s1)  <- ncu profiles this
    cudaEventRecord(e1, s1);                          // join marker

    k_gemm<<<NB_GEMM, 128>>>(x, bS);                  // launch 4 (origin, overlaps s1 chain)
    cudaStreamWaitEvent(0, e1, 0);                    // join
    k_agg<<<NN / 8, 256>>>(bM, bA);                   // launch 5
    k_mlp<<<(NN + 127) / 128, 256>>>(W1, b1, W2, b2, out);  // launch 6
    // streams/events intentionally not destroyed: kernel_launch is invoked only for
    // the correctness run and the capture run; destroying capture-referenced objects
    // mid-capture is riskier than the tiny handle leak.
}

// round 10
// speedup vs baseline: 1.0216x; 1.0216x over previous
#include <cuda_runtime.h>
#include <cuda_bf16.h>
#include <math_constants.h>
#include <cstdint>

#define NN 50000
#define NE 1600000
#define FIN 264
#define FH 48
#define FC 144
#define FM 64
#define KPAD 272                      // 264 padded to 17 chunks of 16
#define NPAD 50048
#define GM 64                         // gemm rows per CTA
#define GSTR 24                       // smem row stride in u16 (48B, conflict-free)
#define NCH 17

#define NB_EDGES 6250                 // NE/256
#define NB_XCONV 6641                 // ceil(NN*34/256)
#define NB_WPACK 153                  // ceil(FC*KPAD/256)
#define NB_GEMM  782                  // 64*782 = 50048

typedef unsigned long long u64;
typedef unsigned int u32;
typedef unsigned short u16;

// ---------------- scratch (static __device__ globals; zero-init, no allocs) ----------------
__device__ int   g_row[NE];
__device__ int   g_col[NE];
__device__ float g_deg[NN];           // Σ edge weight; RE-ZEROED by k_scan each call
__device__ int   g_count[NN];         // in-degree; RE-ZEROED by k_scan each call
__device__ float g_dis[NN];           // rsqrt(1+deg)
__device__ int   g_off[NN + 1];
__device__ int   g_cursor[NN];
__device__ int2  g_csr[NE];
__device__ float g_H[(size_t)NN * FC];
__device__ float g_Y[(size_t)NN * FC];
__device__ u16   g_xh[(size_t)NPAD * KPAD];   // x split-bf16 hi, row-major, zero-padded
__device__ u16   g_xl[(size_t)NPAD * KPAD];   // x split-bf16 lo
__device__ u16   g_Wh[(size_t)FC * KPAD];     // [WM|WA|WS] hi, n-major (transposed)
__device__ u16   g_Wl[(size_t)FC * KPAD];     // lo

// ---------------- helpers ----------------
__device__ __forceinline__ void ffma2(u64& d, u64 a, u64 b) {
    asm("fma.rn.f32x2 %0, %1, %2, %0;" : "+l"(d) : "l"(a), "l"(b));
}
__device__ __forceinline__ u64 dup2(float v) {
    u32 u = __float_as_uint(v);
    return (u64)u | ((u64)u << 32);
}
__device__ __forceinline__ float lo2(u64 v) { return __uint_as_float((u32)v); }
__device__ __forceinline__ float hi2(u64 v) { return __uint_as_float((u32)(v >> 32)); }
__device__ __forceinline__ u32 smem_u32(const void* p) {
    u32 a;
    asm("{ .reg .u64 t; cvta.to.shared.u64 t, %1; cvt.u32.u64 %0, t; }" : "=r"(a) : "l"(p));
    return a;
}
__device__ __forceinline__ void cpa16(u32 dst, const void* src) {
    asm volatile("cp.async.cg.shared.global [%0], [%1], 16;" :: "r"(dst), "l"(src));
}
#define CPA_COMMIT() asm volatile("cp.async.commit_group;" ::: "memory")
#define CPA_WAIT1()  asm volatile("cp.async.wait_group 1;" ::: "memory")
#define CPA_WAIT0()  asm volatile("cp.async.wait_group 0;" ::: "memory")

// bf16 HMMA: D[16x8] += A[16x16] * B[16x8], fp32 accum (baseline PTX, fallback HMMA on sm_103)
__device__ __forceinline__ void mma_bf16(float* c, u32 a0, u32 a1, u32 a2, u32 a3, u32 b0, u32 b1) {
    asm volatile(
        "mma.sync.aligned.m16n8k16.row.col.f32.bf16.bf16.f32 "
        "{%0,%1,%2,%3}, {%4,%5,%6,%7}, {%8,%9}, {%0,%1,%2,%3};"
        : "+f"(c[0]), "+f"(c[1]), "+f"(c[2]), "+f"(c[3])
        : "r"(a0), "r"(a1), "r"(a2), "r"(a3), "r"(b0), "r"(b1));
}

__device__ __forceinline__ void split_bf16(float v, u16& h, u16& l) {
    __nv_bfloat16 hh = __float2bfloat16(v);
    float r = v - __bfloat162float(hh);
    __nv_bfloat16 ll = __float2bfloat16(r);
    h = __bfloat16_as_ushort(hh);
    l = __bfloat16_as_ushort(ll);
}

// ================= mega_xw: xconv ∪ wpack (origin-stream pre-GEMM work) =================
__global__ __launch_bounds__(256) void k_mega_xw(const float* __restrict__ x,
                                                 const float* __restrict__ WM,
                                                 const float* __restrict__ WA,
                                                 const float* __restrict__ WS) {
    int bid = blockIdx.x;
    int tid = threadIdx.x;
    if (bid < NB_XCONV) {
        // ---- x -> split-bf16 hi/lo, row-major, K padded to 272 ----
        int idx = bid * 256 + tid;
        if (idx < NN * 34) {
            int row = idx / 34, seg = idx - (idx / 34) * 34;
            int k0 = seg * 8;
            u16 h[8], l[8];
#pragma unroll
            for (int i = 0; i < 8; i++) {
                int k = k0 + i;
                float v = (k < FIN) ? x[(size_t)row * FIN + k] : 0.f;
                split_bf16(v, h[i], l[i]);
            }
            uint4 vh, vl;
            vh.x = (u32)h[0] | ((u32)h[1] << 16); vh.y = (u32)h[2] | ((u32)h[3] << 16);
            vh.z = (u32)h[4] | ((u32)h[5] << 16); vh.w = (u32)h[6] | ((u32)h[7] << 16);
            vl.x = (u32)l[0] | ((u32)l[1] << 16); vl.y = (u32)l[2] | ((u32)l[3] << 16);
            vl.z = (u32)l[4] | ((u32)l[5] << 16); vl.w = (u32)l[6] | ((u32)l[7] << 16);
            *(uint4*)&g_xh[(size_t)row * KPAD + k0] = vh;
            *(uint4*)&g_xl[(size_t)row * KPAD + k0] = vl;
        }
    } else {
        // ---- weights -> split-bf16, n-major [144][KPAD] ----
        int idx = (bid - NB_XCONV) * 256 + tid;
        if (idx < FC * KPAD) {
            int c = idx / KPAD, k = idx - c * KPAD;
            float v = 0.f;
            if (k < FIN)
                v = (c < 48) ? WM[k * FH + c] : (c < 96) ? WA[k * FH + c - 48] : WS[k * FH + c - 96];
            u16 h, l;
            split_bf16(v, h, l);
            g_Wh[(size_t)c * KPAD + k] = h;
            g_Wl[(size_t)c * KPAD + k] = l;
        }
    }
}

// ---------------- extract edges + degree/in-degree histogram ----------------
__global__ __launch_bounds__(256) void k_edges(const int* __restrict__ ei32,
                                               const float* __restrict__ ew) {
    __shared__ int s_is64;
    int tid = threadIdx.x;
    if (tid == 0) {
        int all0 = 1;
        for (int k = 0; k < 32; k++)
            if (ei32[2 * k + 1] != 0) { all0 = 0; break; }
        s_is64 = all0;   // int64 LE with values<2^31 -> odd words all zero
    }
    __syncthreads();
    int e = blockIdx.x * 256 + tid;
    if (e < NE) {
        int row, col;
        if (s_is64) { row = ei32[2 * e]; col = ei32[2 * (NE + e)]; }
        else        { row = ei32[e];     col = ei32[NE + e]; }
        g_row[e] = row;
        g_col[e] = col;
        atomicAdd(&g_deg[col], ew[e]);
        atomicAdd(&g_count[col], 1);
    }
}

// ---------------- scan: dis = rsqrt(1+deg), exclusive scan of counts, reset accumulators ----------------
__global__ void k_scan() {
    __shared__ int s[1024];
    int tid = threadIdx.x;
    for (int i = tid; i < NN; i += 1024) {
        g_dis[i] = rsqrtf(1.0f + g_deg[i]);
        g_deg[i] = 0.f;                      // reset for next graph replay
    }

    const int CH = (NN + 1023) / 1024;
    int lo = tid * CH;
    int hi = lo + CH; if (hi > NN) hi = NN;
    int sum = 0;
    for (int i = lo; i < hi; i++) sum += g_count[i];
    s[tid] = sum;
    __syncthreads();
    for (int off = 1; off < 1024; off <<= 1) {
        int t = (tid >= off) ? s[tid - off] : 0;
        __syncthreads();
        s[tid] += t;
        __syncthreads();
    }
    int run = s[tid] - sum;
    for (int i = lo; i < hi; i++) {
        int c = g_count[i];
        g_off[i] = run; g_cursor[i] = run;
        g_count[i] = 0;                      // reset for next graph replay
        run += c;
    }
    if (tid == 1023) g_off[NN] = run;
}

// ---------------- CSR scatter ----------------
__global__ void k_csr(const float* __restrict__ ew) {
    int e = blockIdx.x * blockDim.x + threadIdx.x;
    if (e < NE) {
        int row = g_row[e];
        int col = g_col[e];
        float nrm = g_dis[row] * ew[e] * g_dis[col];
        int pos = atomicAdd(&g_cursor[col], 1);
        g_csr[pos] = make_int2(row, __float_as_int(nrm));
    }
}

// ---------------- GEMM1 on HMMA: H = x @ [WM|WA|WS] via split-bf16 (3 products) ----------------
__global__ void __launch_bounds__(128, 4) k_gemm(const float* __restrict__ bS) {
    __shared__ u16 sA[2][2][GM * GSTR];    // [buf][hi/lo][row*24 + k] : 12 KB
    __shared__ u16 sB[2][2][FC * GSTR];    // [buf][hi/lo][n*24 + k]   : 27.6 KB
    int tid = threadIdx.x;
    int w = tid >> 5, lane = tid & 31;
    int gr = lane >> 2, kp = lane & 3;
    int row0 = blockIdx.x * GM;

    float acc[18][4];
#pragma unroll
    for (int i = 0; i < 18; i++) { acc[i][0] = acc[i][1] = acc[i][2] = acc[i][3] = 0.f; }

    auto load_ab = [&](int ch) {
        int buf = ch & 1;
        int kt = ch * 16;
        // A: 64 rows x 16 bf16 x 2 splits = 256 x 16B granules (2 per thread)
#pragma unroll
        for (int l = 0; l < 2; l++) {
            int idx = tid + l * 128;
            int split = idx >> 7;
            int r2 = idx & 127;
            int row = r2 >> 1, half = r2 & 1;
            const u16* src = (split ? g_xl : g_xh) + (size_t)(row0 + row) * KPAD + kt + half * 8;
            cpa16(smem_u32(&sA[buf][split][row * GSTR + half * 8]), src);
        }
        // B: 144 rows x 16 bf16 x 2 splits = 576 granules
#pragma unroll
        for (int l = 0; l < 5; l++) {
            int idx = tid + l * 128;
            if (idx < 576) {
                int split = (idx >= 288) ? 1 : 0;
                int e = idx - split * 288;
                int n = e >> 1, half = e & 1;
                const u16* src = (split ? g_Wl : g_Wh) + (size_t)n * KPAD + kt + half * 8;
                cpa16(smem_u32(&sB[buf][split][n * GSTR + half * 8]), src);
            }
        }
        CPA_COMMIT();
    };

    load_ab(0);
    load_ab(1);

    int aoff = (w * 16 + gr) * GSTR + kp * 2;   // u16 index of a0
    int boff = gr * GSTR + kp * 2;              // u16 index within n-tile

    for (int ch = 0; ch < NCH; ch++) {
        int buf = ch & 1;
        if (ch < NCH - 1) CPA_WAIT1(); else CPA_WAIT0();
        __syncthreads();

        u32 ah0 = *(const u32*)&sA[buf][0][aoff];
        u32 ah1 = *(const u32*)&sA[buf][0][aoff + 8 * GSTR];
        u32 ah2 = *(const u32*)&sA[buf][0][aoff + 8];
        u32 ah3 = *(const u32*)&sA[buf][0][aoff + 8 * GSTR + 8];
        u32 al0 = *(const u32*)&sA[buf][1][aoff];
        u32 al1 = *(const u32*)&sA[buf][1][aoff + 8 * GSTR];
        u32 al2 = *(const u32*)&sA[buf][1][aoff + 8];
        u32 al3 = *(const u32*)&sA[buf][1][aoff + 8 * GSTR + 8];

#pragma unroll
        for (int nt = 0; nt < 18; nt++) {
            int bo = nt * 8 * GSTR + boff;
            u32 bh0 = *(const u32*)&sB[buf][0][bo];
            u32 bh1 = *(const u32*)&sB[buf][0][bo + 8];
            u32 bl0 = *(const u32*)&sB[buf][1][bo];
            u32 bl1 = *(const u32*)&sB[buf][1][bo + 8];
            mma_bf16(acc[nt], ah0, ah1, ah2, ah3, bh0, bh1);   // xh*wh
            mma_bf16(acc[nt], ah0, ah1, ah2, ah3, bl0, bl1);   // xh*wl
            mma_bf16(acc[nt], al0, al1, al2, al3, bh0, bh1);   // xl*wh
        }
        __syncthreads();
        if (ch + 2 < NCH) load_ab(ch + 2);
    }

    // epilogue: thread holds rows (gr, gr+8) of warp slab, cols nt*8 + kp*2 (+1)
    int r1 = row0 + w * 16 + gr;
    int r2 = r1 + 8;
#pragma unroll
    for (int nt = 0; nt < 18; nt++) {
        int n0 = nt * 8 + kp * 2;
        float v0 = acc[nt][0], v1 = acc[nt][1], v2 = acc[nt][2], v3 = acc[nt][3];
        if (n0 >= 96) {
            float b0 = bS[n0 - 96], b1 = bS[n0 - 95];
            v0 = fmaxf(v0 + b0, 0.f); v1 = fmaxf(v1 + b1, 0.f);
            v2 = fmaxf(v2 + b0, 0.f); v3 = fmaxf(v3 + b1, 0.f);
        }
        if (r1 < NN) *(float2*)&g_H[(size_t)r1 * FC + n0] = make_float2(v0, v1);
        if (r2 < NN) *(float2*)&g_H[(size_t)r2 * FC + n0] = make_float2(v2, v3);
    }
}

// ---------------- aggregation: 1 warp per node, 8 lanes per edge, no atomics ----------------
__global__ __launch_bounds__(256) void k_agg(const float* __restrict__ bM, const float* __restrict__ bA) {
    __shared__ float sb[96];
    int tid = threadIdx.x;
    if (tid < 96) sb[tid] = (tid < 48) ? bM[tid] : bA[tid - 48];
    __syncthreads();

    int wid = tid >> 5;
    int i = blockIdx.x * 8 + wid;
    int lane = tid & 31;
    int group = lane >> 3;
    int gl = lane & 7;
    bool m1 = (gl < 4);
    const float NINF = -CUDART_INF_F;

    const float* Hrow = g_H + (size_t)i * FC;
    float4 acc0, acc1, acc2;
    if (group == 0) {
        float dii = g_dis[i];
        float sm = dii * dii;
        float4 v0 = *(const float4*)(Hrow + gl * 4);
        float4 v1 = *(const float4*)(Hrow + 32 + gl * 4);
        float4 v2 = *(const float4*)(Hrow + 64 + gl * 4);
        acc0 = make_float4(sm * v0.x, sm * v0.y, sm * v0.z, sm * v0.w);
        acc1 = make_float4(sm * v1.x, sm * v1.y, sm * v1.z, sm * v1.w);
        acc2 = make_float4(sm * v2.x, sm * v2.y, sm * v2.z, sm * v2.w);
    } else {
        acc0 = make_float4(NINF, NINF, NINF, NINF);
        float i1 = m1 ? NINF : 0.f;
        acc1 = make_float4(i1, i1, i1, i1);
        acc2 = make_float4(0.f, 0.f, 0.f, 0.f);
    }

    int s0 = g_off[i], s1 = g_off[i + 1];
    for (int j = s0 + group; j < s1; j += 4) {
        int2 p = g_csr[j];
        const float* Hr = g_H + (size_t)p.x * FC;
        float nrm = __int_as_float(p.y);
        float4 v0 = *(const float4*)(Hr + gl * 4);
        float4 v1 = *(const float4*)(Hr + 32 + gl * 4);
        float4 v2 = *(const float4*)(Hr + 64 + gl * 4);
        acc0.x = fmaxf(acc0.x, nrm * v0.x); acc0.y = fmaxf(acc0.y, nrm * v0.y);
        acc0.z = fmaxf(acc0.z, nrm * v0.z); acc0.w = fmaxf(acc0.w, nrm * v0.w);
        if (m1) {
            acc1.x = fmaxf(acc1.x, nrm * v1.x); acc1.y = fmaxf(acc1.y, nrm * v1.y);
            acc1.z = fmaxf(acc1.z, nrm * v1.z); acc1.w = fmaxf(acc1.w, nrm * v1.w);
        } else {
            acc1.x = fmaf(nrm, v1.x, acc1.x); acc1.y = fmaf(nrm, v1.y, acc1.y);
            acc1.z = fmaf(nrm, v1.z, acc1.z); acc1.w = fmaf(nrm, v1.w, acc1.w);
        }
        acc2.x = fmaf(nrm, v2.x, acc2.x); acc2.y = fmaf(nrm, v2.y, acc2.y);
        acc2.z = fmaf(nrm, v2.z, acc2.z); acc2.w = fmaf(nrm, v2.w, acc2.w);
    }

#pragma unroll
    for (int d = 8; d <= 16; d <<= 1) {
        float t;
        t = __shfl_xor_sync(0xffffffffu, acc0.x, d); acc0.x = fmaxf(acc0.x, t);
        t = __shfl_xor_sync(0xffffffffu, acc0.y, d); acc0.y = fmaxf(acc0.y, t);
        t = __shfl_xor_sync(0xffffffffu, acc0.z, d); acc0.z = fmaxf(acc0.z, t);
        t = __shfl_xor_sync(0xffffffffu, acc0.w, d); acc0.w = fmaxf(acc0.w, t);
        t = __shfl_xor_sync(0xffffffffu, acc1.x, d); acc1.x = m1 ? fmaxf(acc1.x, t) : acc1.x + t;
        t = __shfl_xor_sync(0xffffffffu, acc1.y, d); acc1.y = m1 ? fmaxf(acc1.y, t) : acc1.y + t;
        t = __shfl_xor_sync(0xffffffffu, acc1.z, d); acc1.z = m1 ? fmaxf(acc1.z, t) : acc1.z + t;
        t = __shfl_xor_sync(0xffffffffu, acc1.w, d); acc1.w = m1 ? fmaxf(acc1.w, t) : acc1.w + t;
        t = __shfl_xor_sync(0xffffffffu, acc2.x, d); acc2.x += t;
        t = __shfl_xor_sync(0xffffffffu, acc2.y, d); acc2.y += t;
        t = __shfl_xor_sync(0xffffffffu, acc2.z, d); acc2.z += t;
        t = __shfl_xor_sync(0xffffffffu, acc2.w, d); acc2.w += t;
    }

    float* Yrow = g_Y + (size_t)i * FC;
    if (group == 0) {
        int o0 = gl * 4, o1 = 32 + gl * 4, o2 = 64 + gl * 4;
        float4 y0 = make_float4(fmaxf(acc0.x + sb[o0 + 0], 0.f), fmaxf(acc0.y + sb[o0 + 1], 0.f),
                                fmaxf(acc0.z + sb[o0 + 2], 0.f), fmaxf(acc0.w + sb[o0 + 3], 0.f));
        float4 y1 = make_float4(fmaxf(acc1.x + sb[o1 + 0], 0.f), fmaxf(acc1.y + sb[o1 + 1], 0.f),
                                fmaxf(acc1.z + sb[o1 + 2], 0.f), fmaxf(acc1.w + sb[o1 + 3], 0.f));
        float4 y2 = make_float4(fmaxf(acc2.x + sb[o2 + 0], 0.f), fmaxf(acc2.y + sb[o2 + 1], 0.f),
                                fmaxf(acc2.z + sb[o2 + 2], 0.f), fmaxf(acc2.w + sb[o2 + 3], 0.f));
        *(float4*)(Yrow + o0) = y0;
        *(float4*)(Yrow + o1) = y1;
        *(float4*)(Yrow + o2) = y2;
    }
    if (lane >= 8 && lane < 20) {
        int o = 96 + (lane - 8) * 4;
        *(float4*)(Yrow + o) = *(const float4*)(Hrow + o);
    }
}

// ---------------- MLP head: out = relu(Y @ W1 + b1) @ W2 + b2  — FFMA2 ----------------
__global__ __launch_bounds__(256) void k_mlp(const float* __restrict__ W1, const float* __restrict__ b1,
                                             const float* __restrict__ W2, const float* __restrict__ b2,
                                             float* __restrict__ out) {
    __shared__ float W1s[FC * FM];
    __shared__ float As[16][132];
    __shared__ float b1s[FM], W2s[FM];
    int tid = threadIdx.x;
    for (int idx = tid; idx < FC * FM; idx += 256) W1s[idx] = W1[idx];
    if (tid < FM) { b1s[tid] = b1[tid]; W2s[tid] = W2[tid]; }
    __syncthreads();

    int tx = tid & 15, ty = tid >> 4;
    int row0 = blockIdx.x * 128;
    u64 acc[8][2];
#pragma unroll
    for (int r = 0; r < 8; r++) { acc[r][0] = 0ull; acc[r][1] = 0ull; }

    for (int kt = 0; kt < FC; kt += 16) {
        {
            int m = tid >> 1;
            int kb = (tid & 1) * 8;
            int row = row0 + m;
            float4 v0 = make_float4(0.f, 0.f, 0.f, 0.f), v1 = v0;
            if (row < NN) {
                v0 = *(const float4*)&g_Y[(size_t)row * FC + kt + kb];
                v1 = *(const float4*)&g_Y[(size_t)row * FC + kt + kb + 4];
            }
            As[kb + 0][m] = v0.x; As[kb + 1][m] = v0.y; As[kb + 2][m] = v0.z; As[kb + 3][m] = v0.w;
            As[kb + 4][m] = v1.x; As[kb + 5][m] = v1.y; As[kb + 6][m] = v1.z; As[kb + 7][m] = v1.w;
        }
        __syncthreads();
#pragma unroll
        for (int kk = 0; kk < 16; kk++) {
            u64 bb0 = *(const u64*)&W1s[(kt + kk) * FM + tx * 4];
            u64 bb1 = *(const u64*)&W1s[(kt + kk) * FM + tx * 4 + 2];
#pragma unroll
            for (int r = 0; r < 8; r++) {
                u64 aa = dup2(As[kk][ty * 8 + r]);
                ffma2(acc[r][0], aa, bb0);
                ffma2(acc[r][1], aa, bb1);
            }
        }
        __syncthreads();
    }

    float part[8];
    int c0 = tx * 4;
#pragma unroll
    for (int r = 0; r < 8; r++) {
        float t0 = fmaxf(lo2(acc[r][0]) + b1s[c0 + 0], 0.f);
        float t1 = fmaxf(hi2(acc[r][0]) + b1s[c0 + 1], 0.f);
        float t2 = fmaxf(lo2(acc[r][1]) + b1s[c0 + 2], 0.f);
        float t3 = fmaxf(hi2(acc[r][1]) + b1s[c0 + 3], 0.f);
        part[r] = t0 * W2s[c0] + t1 * W2s[c0 + 1] + t2 * W2s[c0 + 2] + t3 * W2s[c0 + 3];
    }
#pragma unroll
    for (int d = 1; d < 16; d <<= 1)
#pragma unroll
        for (int r = 0; r < 8; r++) part[r] += __shfl_xor_sync(0xffffffffu, part[r], d);

    if (tx == 0) {
        float bb = b2[0];
#pragma unroll
        for (int r = 0; r < 8; r++) {
            int row = row0 + ty * 8 + r;
            if (row < NN) out[row] = part[r] + bb;
        }
    }
}

// ---------------- launch: R8 kernels + fork-join streams (the ONLY change vs R8) ----------------
// origin:  mega_xw ───────────► gemm ──(wait e1)─► agg ─► mlp
// side s1: (wait e0) edges ► scan ► csr ──record e1─┘
extern "C" void kernel_launch(void* const* d_in, const int* in_sizes, int n_in,
                              void* d_out, int out_size) {
    const float* x  = (const float*)d_in[0];
    const int*   ei = (const int*)d_in[1];
    const float* ew = (const float*)d_in[2];
    const float* WM = (const float*)d_in[3];
    const float* bM = (const float*)d_in[4];
    const float* WA = (const float*)d_in[5];
    const float* bA = (const float*)d_in[6];
    const float* WS = (const float*)d_in[7];
    const float* bS = (const float*)d_in[8];
    const float* W1 = (const float*)d_in[9];
    const float* b1 = (const float*)d_in[10];
    const float* W2 = (const float*)d_in[11];
    const float* b2 = (const float*)d_in[12];
    float* out = (float*)d_out;

    cudaStream_t s1;
    cudaEvent_t e0, e1;
    cudaStreamCreateWithFlags(&s1, cudaStreamNonBlocking);
    cudaEventCreateWithFlags(&e0, cudaEventDisableTiming);
    cudaEventCreateWithFlags(&e1, cudaEventDisableTiming);

    cudaEventRecord(e0, 0);                               // fork from capture origin
    cudaStreamWaitEvent(s1, e0, 0);

    k_mega_xw<<<NB_XCONV + NB_WPACK, 256>>>(x, WM, WA, WS);    // launch 0 (origin)
    k_edges<<<NB_EDGES, 256, 0, s1>>>(ei, ew);                 // launch 1 (s1)
    k_scan<<<1, 1024, 0, s1>>>();                              // launch 2 (s1)
    k_gemm<<<NB_GEMM, 128>>>(bS);                              // launch 3 (origin) <- ncu
    k_csr<<<NB_EDGES, 256, 0, s1>>>(ew);                       // launch 4 (s1)
    cudaEventRecord(e1, s1);                                   // join marker

    cudaStreamWaitEvent(0, e1, 0);                             // join
    k_agg<<<NN / 8, 256>>>(bM, bA);                            // launch 5
    k_mlp<<<(NN + 127) / 128, 256>>>(W1, b1, W2, b2, out);     // launch 6
    // streams/events intentionally not destroyed (capture-referenced; tiny handle leak)
}

// round 11
// speedup vs baseline: 1.0357x; 1.0138x over previous
#include <cuda_runtime.h>
#include <cuda_bf16.h>
#include <math_constants.h>
#include <cstdint>

#define NN 50000
#define NE 1600000
#define FIN 264
#define FH 48
#define FC 144
#define FM 64
#define KPAD 272                      // 264 padded to 17 chunks of 16
#define NPAD 50048
#define GM 64                         // gemm rows per CTA
#define GSTR 24                       // smem row stride in u16 (48B, conflict-free)
#define NCH 17

#define NB_EDGES 6250                 // NE/256
#define NB_XCONV 6641                 // ceil(NN*34/256)
#define NB_WPACK 153                  // ceil(FC*KPAD/256)
#define NB_GEMM  782                  // 64*782 = 50048

typedef unsigned long long u64;
typedef unsigned int u32;
typedef unsigned short u16;

// ---------------- scratch (static __device__ globals; zero-init, no allocs) ----------------
__device__ int   g_row[NE];
__device__ int   g_col[NE];
__device__ float g_deg[NN];           // Σ edge weight; RE-ZEROED by k_scan each call
__device__ int   g_count[NN];         // in-degree; RE-ZEROED by k_scan each call
__device__ float g_dis[NN];           // rsqrt(1+deg)
__device__ int   g_off[NN + 1];
__device__ int   g_cursor[NN];
__device__ int2  g_csr[NE];
__device__ float g_H[(size_t)NN * FC];
__device__ float g_Y[(size_t)NN * FC];
__device__ u16   g_xh[(size_t)NPAD * KPAD];   // x split-bf16 hi, row-major, zero-padded
__device__ u16   g_xl[(size_t)NPAD * KPAD];   // x split-bf16 lo
__device__ u16   g_Wh[(size_t)FC * KPAD];     // [WM|WA|WS] hi, n-major (transposed)
__device__ u16   g_Wl[(size_t)FC * KPAD];     // lo

// ---------------- helpers ----------------
__device__ __forceinline__ void ffma2(u64& d, u64 a, u64 b) {
    asm("fma.rn.f32x2 %0, %1, %2, %0;" : "+l"(d) : "l"(a), "l"(b));
}
__device__ __forceinline__ u64 dup2(float v) {
    u32 u = __float_as_uint(v);
    return (u64)u | ((u64)u << 32);
}
__device__ __forceinline__ float lo2(u64 v) { return __uint_as_float((u32)v); }
__device__ __forceinline__ float hi2(u64 v) { return __uint_as_float((u32)(v >> 32)); }
__device__ __forceinline__ u32 smem_u32(const void* p) {
    u32 a;
    asm("{ .reg .u64 t; cvta.to.shared.u64 t, %1; cvt.u32.u64 %0, t; }" : "=r"(a) : "l"(p));
    return a;
}
__device__ __forceinline__ void cpa16(u32 dst, const void* src) {
    asm volatile("cp.async.cg.shared.global [%0], [%1], 16;" :: "r"(dst), "l"(src));
}
#define CPA_COMMIT() asm volatile("cp.async.commit_group;" ::: "memory")
#define CPA_WAIT1()  asm volatile("cp.async.wait_group 1;" ::: "memory")
#define CPA_WAIT0()  asm volatile("cp.async.wait_group 0;" ::: "memory")

// bf16 HMMA: D[16x8] += A[16x16] * B[16x8], fp32 accum (baseline PTX, fallback HMMA on sm_103)
__device__ __forceinline__ void mma_bf16(float* c, u32 a0, u32 a1, u32 a2, u32 a3, u32 b0, u32 b1) {
    asm volatile(
        "mma.sync.aligned.m16n8k16.row.col.f32.bf16.bf16.f32 "
        "{%0,%1,%2,%3}, {%4,%5,%6,%7}, {%8,%9}, {%0,%1,%2,%3};"
        : "+f"(c[0]), "+f"(c[1]), "+f"(c[2]), "+f"(c[3])
        : "r"(a0), "r"(a1), "r"(a2), "r"(a3), "r"(b0), "r"(b1));
}

__device__ __forceinline__ void split_bf16(float v, u16& h, u16& l) {
    __nv_bfloat16 hh = __float2bfloat16(v);
    float r = v - __bfloat162float(hh);
    __nv_bfloat16 ll = __float2bfloat16(r);
    h = __bfloat16_as_ushort(hh);
    l = __bfloat16_as_ushort(ll);
}

// ================= mega1: edges ∪ xconv ∪ wpack (independent work, one launch) =================
__global__ __launch_bounds__(256) void k_mega1(const int* __restrict__ ei32,
                                               const float* __restrict__ ew,
                                               const float* __restrict__ x,
                                               const float* __restrict__ WM,
                                               const float* __restrict__ WA,
                                               const float* __restrict__ WS) {
    __shared__ int s_is64;
    int bid = blockIdx.x;
    int tid = threadIdx.x;

    if (bid < NB_EDGES) {
        if (tid == 0) {
            int all0 = 1;
            for (int k = 0; k < 32; k++)
                if (ei32[2 * k + 1] != 0) { all0 = 0; break; }
            s_is64 = all0;   // int64 LE with values<2^31 -> odd words all zero
        }
        __syncthreads();
        int e = bid * 256 + tid;
        if (e < NE) {
            int row, col;
            if (s_is64) { row = ei32[2 * e]; col = ei32[2 * (NE + e)]; }
            else        { row = ei32[e];     col = ei32[NE + e]; }
            g_row[e] = row;
            g_col[e] = col;
            atomicAdd(&g_deg[col], ew[e]);
            atomicAdd(&g_count[col], 1);
        }
    } else if (bid < NB_EDGES + NB_XCONV) {
        // ---- x -> split-bf16 hi/lo, row-major, K padded to 272 ----
        int idx = (bid - NB_EDGES) * 256 + tid;
        if (idx < NN * 34) {
            int row = idx / 34, seg = idx - (idx / 34) * 34;
            int k0 = seg * 8;
            u16 h[8], l[8];
#pragma unroll
            for (int i = 0; i < 8; i++) {
                int k = k0 + i;
                float v = (k < FIN) ? x[(size_t)row * FIN + k] : 0.f;
                split_bf16(v, h[i], l[i]);
            }
            uint4 vh, vl;
            vh.x = (u32)h[0] | ((u32)h[1] << 16); vh.y = (u32)h[2] | ((u32)h[3] << 16);
            vh.z = (u32)h[4] | ((u32)h[5] << 16); vh.w = (u32)h[6] | ((u32)h[7] << 16);
            vl.x = (u32)l[0] | ((u32)l[1] << 16); vl.y = (u32)l[2] | ((u32)l[3] << 16);
            vl.z = (u32)l[4] | ((u32)l[5] << 16); vl.w = (u32)l[6] | ((u32)l[7] << 16);
            *(uint4*)&g_xh[(size_t)row * KPAD + k0] = vh;
            *(uint4*)&g_xl[(size_t)row * KPAD + k0] = vl;
        }
    } else {
        // ---- weights -> split-bf16, n-major [144][KPAD] ----
        int idx = (bid - NB_EDGES - NB_XCONV) * 256 + tid;
        if (idx < FC * KPAD) {
            int c = idx / KPAD, k = idx - c * KPAD;
            float v = 0.f;
            if (k < FIN)
                v = (c < 48) ? WM[k * FH + c] : (c < 96) ? WA[k * FH + c - 48] : WS[k * FH + c - 96];
            u16 h, l;
            split_bf16(v, h, l);
            g_Wh[(size_t)c * KPAD + k] = h;
            g_Wl[(size_t)c * KPAD + k] = l;
        }
    }
}

// ---------------- scan: dis = rsqrt(1+deg), exclusive scan of counts, reset accumulators ----------------
__global__ void k_scan() {
    __shared__ int s[1024];
    int tid = threadIdx.x;
    for (int i = tid; i < NN; i += 1024) {
        g_dis[i] = rsqrtf(1.0f + g_deg[i]);
        g_deg[i] = 0.f;                      // reset for next graph replay
    }

    const int CH = (NN + 1023) / 1024;
    int lo = tid * CH;
    int hi = lo + CH; if (hi > NN) hi = NN;
    int sum = 0;
    for (int i = lo; i < hi; i++) sum += g_count[i];
    s[tid] = sum;
    __syncthreads();
    for (int off = 1; off < 1024; off <<= 1) {
        int t = (tid >= off) ? s[tid - off] : 0;
        __syncthreads();
        s[tid] += t;
        __syncthreads();
    }
    int run = s[tid] - sum;
    for (int i = lo; i < hi; i++) {
        int c = g_count[i];
        g_off[i] = run; g_cursor[i] = run;
        g_count[i] = 0;                      // reset for next graph replay
        run += c;
    }
    if (tid == 1023) g_off[NN] = run;
}

// ---------------- CSR scatter ----------------
__global__ void k_csr(const float* __restrict__ ew) {
    int e = blockIdx.x * blockDim.x + threadIdx.x;
    if (e < NE) {
        int row = g_row[e];
        int col = g_col[e];
        float nrm = g_dis[row] * ew[e] * g_dis[col];
        int pos = atomicAdd(&g_cursor[col], 1);
        g_csr[pos] = make_int2(row, __float_as_int(nrm));
    }
}

// ---------------- GEMM1 on HMMA: H = x @ [WM|WA|WS] via split-bf16 (3 products) ----------------
__global__ void __launch_bounds__(128, 4) k_gemm(const float* __restrict__ bS) {
    __shared__ u16 sA[2][2][GM * GSTR];    // [buf][hi/lo][row*24 + k] : 12 KB
    __shared__ u16 sB[2][2][FC * GSTR];    // [buf][hi/lo][n*24 + k]   : 27.6 KB
    int tid = threadIdx.x;
    int w = tid >> 5, lane = tid & 31;
    int gr = lane >> 2, kp = lane & 3;
    int row0 = blockIdx.x * GM;

    float acc[18][4];
#pragma unroll
    for (int i = 0; i < 18; i++) { acc[i][0] = acc[i][1] = acc[i][2] = acc[i][3] = 0.f; }

    auto load_ab = [&](int ch) {
        int buf = ch & 1;
        int kt = ch * 16;
#pragma unroll
        for (int l = 0; l < 2; l++) {
            int idx = tid + l * 128;
            int split = idx >> 7;
            int r2 = idx & 127;
            int row = r2 >> 1, half = r2 & 1;
            const u16* src = (split ? g_xl : g_xh) + (size_t)(row0 + row) * KPAD + kt + half * 8;
            cpa16(smem_u32(&sA[buf][split][row * GSTR + half * 8]), src);
        }
#pragma unroll
        for (int l = 0; l < 5; l++) {
            int idx = tid + l * 128;
            if (idx < 576) {
                int split = (idx >= 288) ? 1 : 0;
                int e = idx - split * 288;
                int n = e >> 1, half = e & 1;
                const u16* src = (split ? g_Wl : g_Wh) + (size_t)n * KPAD + kt + half * 8;
                cpa16(smem_u32(&sB[buf][split][n * GSTR + half * 8]), src);
            }
        }
        CPA_COMMIT();
    };

    load_ab(0);
    load_ab(1);

    int aoff = (w * 16 + gr) * GSTR + kp * 2;   // u16 index of a0
    int boff = gr * GSTR + kp * 2;              // u16 index within n-tile

    for (int ch = 0; ch < NCH; ch++) {
        int buf = ch & 1;
        if (ch < NCH - 1) CPA_WAIT1(); else CPA_WAIT0();
        __syncthreads();

        u32 ah0 = *(const u32*)&sA[buf][0][aoff];
        u32 ah1 = *(const u32*)&sA[buf][0][aoff + 8 * GSTR];
        u32 ah2 = *(const u32*)&sA[buf][0][aoff + 8];
        u32 ah3 = *(const u32*)&sA[buf][0][aoff + 8 * GSTR + 8];
        u32 al0 = *(const u32*)&sA[buf][1][aoff];
        u32 al1 = *(const u32*)&sA[buf][1][aoff + 8 * GSTR];
        u32 al2 = *(const u32*)&sA[buf][1][aoff + 8];
        u32 al3 = *(const u32*)&sA[buf][1][aoff + 8 * GSTR + 8];

#pragma unroll
        for (int nt = 0; nt < 18; nt++) {
            int bo = nt * 8 * GSTR + boff;
            u32 bh0 = *(const u32*)&sB[buf][0][bo];
            u32 bh1 = *(const u32*)&sB[buf][0][bo + 8];
            u32 bl0 = *(const u32*)&sB[buf][1][bo];
            u32 bl1 = *(const u32*)&sB[buf][1][bo + 8];
            mma_bf16(acc[nt], ah0, ah1, ah2, ah3, bh0, bh1);   // xh*wh
            mma_bf16(acc[nt], ah0, ah1, ah2, ah3, bl0, bl1);   // xh*wl
            mma_bf16(acc[nt], al0, al1, al2, al3, bh0, bh1);   // xl*wh
        }
        __syncthreads();
        if (ch + 2 < NCH) load_ab(ch + 2);
    }

    // epilogue: thread holds rows (gr, gr+8) of warp slab, cols nt*8 + kp*2 (+1)
    int r1 = row0 + w * 16 + gr;
    int r2 = r1 + 8;
#pragma unroll
    for (int nt = 0; nt < 18; nt++) {
        int n0 = nt * 8 + kp * 2;
        float v0 = acc[nt][0], v1 = acc[nt][1], v2 = acc[nt][2], v3 = acc[nt][3];
        if (n0 >= 96) {
            float b0 = bS[n0 - 96], b1 = bS[n0 - 95];
            v0 = fmaxf(v0 + b0, 0.f); v1 = fmaxf(v1 + b1, 0.f);
            v2 = fmaxf(v2 + b0, 0.f); v3 = fmaxf(v3 + b1, 0.f);
        }
        if (r1 < NN) *(float2*)&g_H[(size_t)r1 * FC + n0] = make_float2(v0, v1);
        if (r2 < NN) *(float2*)&g_H[(size_t)r2 * FC + n0] = make_float2(v2, v3);
    }
}

// ---------------- aggregation: 1 warp/node, 8 lanes/edge, 2x-unrolled gather (MLP 3->6) ----------------
__global__ __launch_bounds__(256) void k_agg(const float* __restrict__ bM, const float* __restrict__ bA) {
    __shared__ float sb[96];
    int tid = threadIdx.x;
    if (tid < 96) sb[tid] = (tid < 48) ? bM[tid] : bA[tid - 48];
    __syncthreads();

    int wid = tid >> 5;
    int i = blockIdx.x * 8 + wid;
    int lane = tid & 31;
    int group = lane >> 3;
    int gl = lane & 7;
    bool m1 = (gl < 4);
    const float NINF = -CUDART_INF_F;

    const float* Hrow = g_H + (size_t)i * FC;
    float4 acc0, acc1, acc2;
    if (group == 0) {
        float dii = g_dis[i];
        float sm = dii * dii;
        float4 v0 = *(const float4*)(Hrow + gl * 4);
        float4 v1 = *(const float4*)(Hrow + 32 + gl * 4);
        float4 v2 = *(const float4*)(Hrow + 64 + gl * 4);
        acc0 = make_float4(sm * v0.x, sm * v0.y, sm * v0.z, sm * v0.w);
        acc1 = make_float4(sm * v1.x, sm * v1.y, sm * v1.z, sm * v1.w);
        acc2 = make_float4(sm * v2.x, sm * v2.y, sm * v2.z, sm * v2.w);
    } else {
        acc0 = make_float4(NINF, NINF, NINF, NINF);
        float i1 = m1 ? NINF : 0.f;
        acc1 = make_float4(i1, i1, i1, i1);
        acc2 = make_float4(0.f, 0.f, 0.f, 0.f);
    }

    int s0 = g_off[i], s1 = g_off[i + 1];
    int j = s0 + group;
    // 2 edges per iteration: all 6 gathers in flight before any accumulate
    for (; j + 4 < s1; j += 8) {
        int2 pa = g_csr[j];
        int2 pb = g_csr[j + 4];
        const float* Ha = g_H + (size_t)pa.x * FC;
        const float* Hb = g_H + (size_t)pb.x * FC;
        float na = __int_as_float(pa.y);
        float nb = __int_as_float(pb.y);
        float4 a0 = *(const float4*)(Ha + gl * 4);
        float4 a1 = *(const float4*)(Ha + 32 + gl * 4);
        float4 a2 = *(const float4*)(Ha + 64 + gl * 4);
        float4 b0 = *(const float4*)(Hb + gl * 4);
        float4 b1v = *(const float4*)(Hb + 32 + gl * 4);
        float4 b2 = *(const float4*)(Hb + 64 + gl * 4);

        acc0.x = fmaxf(acc0.x, na * a0.x); acc0.y = fmaxf(acc0.y, na * a0.y);
        acc0.z = fmaxf(acc0.z, na * a0.z); acc0.w = fmaxf(acc0.w, na * a0.w);
        if (m1) {
            acc1.x = fmaxf(acc1.x, na * a1.x); acc1.y = fmaxf(acc1.y, na * a1.y);
            acc1.z = fmaxf(acc1.z, na * a1.z); acc1.w = fmaxf(acc1.w, na * a1.w);
        } else {
            acc1.x = fmaf(na, a1.x, acc1.x); acc1.y = fmaf(na, a1.y, acc1.y);
            acc1.z = fmaf(na, a1.z, acc1.z); acc1.w = fmaf(na, a1.w, acc1.w);
        }
        acc2.x = fmaf(na, a2.x, acc2.x); acc2.y = fmaf(na, a2.y, acc2.y);
        acc2.z = fmaf(na, a2.z, acc2.z); acc2.w = fmaf(na, a2.w, acc2.w);

        acc0.x = fmaxf(acc0.x, nb * b0.x); acc0.y = fmaxf(acc0.y, nb * b0.y);
        acc0.z = fmaxf(acc0.z, nb * b0.z); acc0.w = fmaxf(acc0.w, nb * b0.w);
        if (m1) {
            acc1.x = fmaxf(acc1.x, nb * b1v.x); acc1.y = fmaxf(acc1.y, nb * b1v.y);
            acc1.z = fmaxf(acc1.z, nb * b1v.z); acc1.w = fmaxf(acc1.w, nb * b1v.w);
        } else {
            acc1.x = fmaf(nb, b1v.x, acc1.x); acc1.y = fmaf(nb, b1v.y, acc1.y);
            acc1.z = fmaf(nb, b1v.z, acc1.z); acc1.w = fmaf(nb, b1v.w, acc1.w);
        }
        acc2.x = fmaf(nb, b2.x, acc2.x); acc2.y = fmaf(nb, b2.y, acc2.y);
        acc2.z = fmaf(nb, b2.z, acc2.z); acc2.w = fmaf(nb, b2.w, acc2.w);
    }
    // tail (at most one edge)
    for (; j < s1; j += 4) {
        int2 p = g_csr[j];
        const float* Hr = g_H + (size_t)p.x * FC;
        float nrm = __int_as_float(p.y);
        float4 v0 = *(const float4*)(Hr + gl * 4);
        float4 v1 = *(const float4*)(Hr + 32 + gl * 4);
        float4 v2 = *(const float4*)(Hr + 64 + gl * 4);
        acc0.x = fmaxf(acc0.x, nrm * v0.x); acc0.y = fmaxf(acc0.y, nrm * v0.y);
        acc0.z = fmaxf(acc0.z, nrm * v0.z); acc0.w = fmaxf(acc0.w, nrm * v0.w);
        if (m1) {
            acc1.x = fmaxf(acc1.x, nrm * v1.x); acc1.y = fmaxf(acc1.y, nrm * v1.y);
            acc1.z = fmaxf(acc1.z, nrm * v1.z); acc1.w = fmaxf(acc1.w, nrm * v1.w);
        } else {
            acc1.x = fmaf(nrm, v1.x, acc1.x); acc1.y = fmaf(nrm, v1.y, acc1.y);
            acc1.z = fmaf(nrm, v1.z, acc1.z); acc1.w = fmaf(nrm, v1.w, acc1.w);
        }
        acc2.x = fmaf(nrm, v2.x, acc2.x); acc2.y = fmaf(nrm, v2.y, acc2.y);
        acc2.z = fmaf(nrm, v2.z, acc2.z); acc2.w = fmaf(nrm, v2.w, acc2.w);
    }

#pragma unroll
    for (int d = 8; d <= 16; d <<= 1) {
        float t;
        t = __shfl_xor_sync(0xffffffffu, acc0.x, d); acc0.x = fmaxf(acc0.x, t);
        t = __shfl_xor_sync(0xffffffffu, acc0.y, d); acc0.y = fmaxf(acc0.y, t);
        t = __shfl_xor_sync(0xffffffffu, acc0.z, d); acc0.z = fmaxf(acc0.z, t);
        t = __shfl_xor_sync(0xffffffffu, acc0.w, d); acc0.w = fmaxf(acc0.w, t);
        t = __shfl_xor_sync(0xffffffffu, acc1.x, d); acc1.x = m1 ? fmaxf(acc1.x, t) : acc1.x + t;
        t = __shfl_xor_sync(0xffffffffu, acc1.y, d); acc1.y = m1 ? fmaxf(acc1.y, t) : acc1.y + t;
        t = __shfl_xor_sync(0xffffffffu, acc1.z, d); acc1.z = m1 ? fmaxf(acc1.z, t) : acc1.z + t;
        t = __shfl_xor_sync(0xffffffffu, acc1.w, d); acc1.w = m1 ? fmaxf(acc1.w, t) : acc1.w + t;
        t = __shfl_xor_sync(0xffffffffu, acc2.x, d); acc2.x += t;
        t = __shfl_xor_sync(0xffffffffu, acc2.y, d); acc2.y += t;
        t = __shfl_xor_sync(0xffffffffu, acc2.z, d); acc2.z += t;
        t = __shfl_xor_sync(0xffffffffu, acc2.w, d); acc2.w += t;
    }

    float* Yrow = g_Y + (size_t)i * FC;
    if (group == 0) {
        int o0 = gl * 4, o1 = 32 + gl * 4, o2 = 64 + gl * 4;
        float4 y0 = make_float4(fmaxf(acc0.x + sb[o0 + 0], 0.f), fmaxf(acc0.y + sb[o0 + 1], 0.f),
                                fmaxf(acc0.z + sb[o0 + 2], 0.f), fmaxf(acc0.w + sb[o0 + 3], 0.f));
        float4 y1 = make_float4(fmaxf(acc1.x + sb[o1 + 0], 0.f), fmaxf(acc1.y + sb[o1 + 1], 0.f),
                                fmaxf(acc1.z + sb[o1 + 2], 0.f), fmaxf(acc1.w + sb[o1 + 3], 0.f));
        float4 y2 = make_float4(fmaxf(acc2.x + sb[o2 + 0], 0.f), fmaxf(acc2.y + sb[o2 + 1], 0.f),
                                fmaxf(acc2.z + sb[o2 + 2], 0.f), fmaxf(acc2.w + sb[o2 + 3], 0.f));
        *(float4*)(Yrow + o0) = y0;
        *(float4*)(Yrow + o1) = y1;
        *(float4*)(Yrow + o2) = y2;
    }
    if (lane >= 8 && lane < 20) {
        int o = 96 + (lane - 8) * 4;
        *(float4*)(Yrow + o) = *(const float4*)(Hrow + o);
    }
}

// ---------------- MLP head: out = relu(Y @ W1 + b1) @ W2 + b2  — FFMA2 ----------------
__global__ __launch_bounds__(256) void k_mlp(const float* __restrict__ W1, const float* __restrict__ b1,
                                             const float* __restrict__ W2, const float* __restrict__ b2,
                                             float* __restrict__ out) {
    __shared__ float W1s[FC * FM];
    __shared__ float As[16][132];
    __shared__ float b1s[FM], W2s[FM];
    int tid = threadIdx.x;
    for (int idx = tid; idx < FC * FM; idx += 256) W1s[idx] = W1[idx];
    if (tid < FM) { b1s[tid] = b1[tid]; W2s[tid] = W2[tid]; }
    __syncthreads();

    int tx = tid & 15, ty = tid >> 4;
    int row0 = blockIdx.x * 128;
    u64 acc[8][2];
#pragma unroll
    for (int r = 0; r < 8; r++) { acc[r][0] = 0ull; acc[r][1] = 0ull; }

    for (int kt = 0; kt < FC; kt += 16) {
        {
            int m = tid >> 1;
            int kb = (tid & 1) * 8;
            int row = row0 + m;
            float4 v0 = make_float4(0.f, 0.f, 0.f, 0.f), v1 = v0;
            if (row < NN) {
                v0 = *(const float4*)&g_Y[(size_t)row * FC + kt + kb];
                v1 = *(const float4*)&g_Y[(size_t)row * FC + kt + kb + 4];
            }
            As[kb + 0][m] = v0.x; As[kb + 1][m] = v0.y; As[kb + 2][m] = v0.z; As[kb + 3][m] = v0.w;
            As[kb + 4][m] = v1.x; As[kb + 5][m] = v1.y; As[kb + 6][m] = v1.z; As[kb + 7][m] = v1.w;
        }
        __syncthreads();
#pragma unroll
        for (int kk = 0; kk < 16; kk++) {
            u64 bb0 = *(const u64*)&W1s[(kt + kk) * FM + tx * 4];
            u64 bb1 = *(const u64*)&W1s[(kt + kk) * FM + tx * 4 + 2];
#pragma unroll
            for (int r = 0; r < 8; r++) {
                u64 aa = dup2(As[kk][ty * 8 + r]);
                ffma2(acc[r][0], aa, bb0);
                ffma2(acc[r][1], aa, bb1);
            }
        }
        __syncthreads();
    }

    float part[8];
    int c0 = tx * 4;
#pragma unroll
    for (int r = 0; r < 8; r++) {
        float t0 = fmaxf(lo2(acc[r][0]) + b1s[c0 + 0], 0.f);
        float t1 = fmaxf(hi2(acc[r][0]) + b1s[c0 + 1], 0.f);
        float t2 = fmaxf(lo2(acc[r][1]) + b1s[c0 + 2], 0.f);
        float t3 = fmaxf(hi2(acc[r][1]) + b1s[c0 + 3], 0.f);
        part[r] = t0 * W2s[c0] + t1 * W2s[c0 + 1] + t2 * W2s[c0 + 2] + t3 * W2s[c0 + 3];
    }
#pragma unroll
    for (int d = 1; d < 16; d <<= 1)
#pragma unroll
        for (int r = 0; r < 8; r++) part[r] += __shfl_xor_sync(0xffffffffu, part[r], d);

    if (tx == 0) {
        float bb = b2[0];
#pragma unroll
        for (int r = 0; r < 8; r++) {
            int row = row0 + ty * 8 + r;
            if (row < NN) out[row] = part[r] + bb;
        }
    }
}

// ---------------- launch: R8 proven 6-launch order (no streams) ----------------
extern "C" void kernel_launch(void* const* d_in, const int* in_sizes, int n_in,
                              void* d_out, int out_size) {
    const float* x  = (const float*)d_in[0];
    const int*   ei = (const int*)d_in[1];
    const float* ew = (const float*)d_in[2];
    const float* WM = (const float*)d_in[3];
    const float* bM = (const float*)d_in[4];
    const float* WA = (const float*)d_in[5];
    const float* bA = (const float*)d_in[6];
    const float* WS = (const float*)d_in[7];
    const float* bS = (const float*)d_in[8];
    const float* W1 = (const float*)d_in[9];
    const float* b1 = (const float*)d_in[10];
    const float* W2 = (const float*)d_in[11];
    const float* b2 = (const float*)d_in[12];
    float* out = (float*)d_out;

    k_mega1<<<NB_EDGES + NB_XCONV + NB_WPACK, 256>>>(ei, ew, x, WM, WA, WS);
    k_scan<<<1, 1024>>>();
    k_csr<<<NB_EDGES, 256>>>(ew);
    k_gemm<<<NB_GEMM, 128>>>(bS);                 // launch 3 <- ncu sanity
    k_agg<<<NN / 8, 256>>>(bM, bA);
    k_mlp<<<(NN + 127) / 128, 256>>>(W1, b1, W2, b2, out);
}